// round 8
// baseline (speedup 1.0000x reference)
#include <cuda_runtime.h>
#include <cuda_fp16.h>
#include <cuda_bf16.h>
#include <cstdint>

// ---------------------------------------------------------------------------
// Problem constants
// ---------------------------------------------------------------------------
#define BATCH   4
#define SEQ     4096
#define DMODEL  1024
#define NHEADS  8
#define HDIM    64
#define STATE   512            // NHEADS*HDIM
#define PROJW   2048           // 4*STATE
#define ROWS    (BATCH*SEQ)    // 16384

// GEMM tiling: block 128x256, 8 warps of 64x64, fp16 HMMA m16n8k16
#define BM 128
#define BN 256
#define NSTAGE 5
#define ROWB 48                         // padded smem row stride (bytes)
#define A_STAGE_B (BM * ROWB)           // 6144 B
#define B_STAGE_B (BN * ROWB)           // 12288 B
#define SMEM_DYN_BYTES (NSTAGE * (A_STAGE_B + B_STAGE_B))   // 92160 B

#define NTILES_N 8                      // 2048 / BN
#define NMTILES  128                    // ROWS / BM

// ---------------------------------------------------------------------------
// Scratch (device globals -- no runtime allocation allowed)
// ---------------------------------------------------------------------------
__device__ float  g_proj[(size_t)ROWS * PROJW];   // [xi_raw | xf | xr | g]
__device__ float  g_y   [(size_t)ROWS * STATE];   // recurrence output
__device__ __half g_xh  [(size_t)ROWS * DMODEL];  // x (fp16)
__device__ __half g_winh[(size_t)PROJW * DMODEL]; // w_in (fp16)
__device__ __half g_wouth[(size_t)DMODEL * STATE];// w_out (fp16)
__device__ __half g_ynh [(size_t)ROWS * STATE];   // gated+normed (fp16)
__device__ int    g_flags[NMTILES];               // per m-tile completion (8 = done)

// ---------------------------------------------------------------------------
// Helpers (scan)
// ---------------------------------------------------------------------------
__device__ __forceinline__ unsigned long long pk2(float lo, float hi) {
    unsigned long long r;
    asm("mov.b64 %0, {%1, %2};" : "=l"(r) : "f"(lo), "f"(hi));
    return r;
}
__device__ __forceinline__ void fma2(unsigned long long& d,
                                     unsigned long long a,
                                     unsigned long long b) {
    asm("fma.rn.f32x2 %0, %1, %2, %0;" : "+l"(d) : "l"(a), "l"(b));
}
__device__ __forceinline__ unsigned long long add2(unsigned long long a,
                                                   unsigned long long b) {
    unsigned long long d;
    asm("add.rn.f32x2 %0, %1, %2;" : "=l"(d) : "l"(a), "l"(b));
    return d;
}
__device__ __forceinline__ float hadd2(unsigned long long v) {
    float a, b;
    asm("mov.b64 {%0, %1}, %2;" : "=f"(a), "=f"(b) : "l"(v));
    return a + b;
}
__device__ __forceinline__ float fsigmoid(float x) {
    return __fdividef(1.0f, 1.0f + __expf(-x));
}
__device__ __forceinline__ float ftanh(float x) {
    float e = __expf(2.0f * x);
    return 1.0f - __fdividef(2.0f, e + 1.0f);
}
__device__ __forceinline__ int ld_acq(const int* p) {
    int v;
    asm volatile("ld.global.acquire.gpu.b32 %0, [%1];" : "=r"(v) : "l"(p));
    return v;
}
__device__ __forceinline__ void wait_flag(const int* p) {
    while (ld_acq(p) < NTILES_N) { __nanosleep(64); }
}
// L2-coherent load: REQUIRED for proj reads produced by concurrent blocks in
// the same kernel (plain/nc loads may return stale read-only-path data).
__device__ __forceinline__ float ldcg(const float* p) {
    float v;
    asm volatile("ld.global.cg.f32 %0, [%1];" : "=f"(v) : "l"(p));
    return v;
}

// ---------------------------------------------------------------------------
// GEMM primitives
// ---------------------------------------------------------------------------
__device__ __forceinline__ void mma_f16(float* c, const uint32_t* a,
                                        uint32_t b0, uint32_t b1) {
    asm volatile(
        "mma.sync.aligned.m16n8k16.row.col.f32.f16.f16.f32 "
        "{%0,%1,%2,%3}, {%4,%5,%6,%7}, {%8,%9}, {%0,%1,%2,%3};\n"
        : "+f"(c[0]), "+f"(c[1]), "+f"(c[2]), "+f"(c[3])
        : "r"(a[0]), "r"(a[1]), "r"(a[2]), "r"(a[3]), "r"(b0), "r"(b1));
}
__device__ __forceinline__ void ldsm4(uint32_t& r0, uint32_t& r1,
                                      uint32_t& r2, uint32_t& r3,
                                      uint32_t addr) {
    asm volatile("ldmatrix.sync.aligned.m8n8.x4.shared.b16 "
                 "{%0,%1,%2,%3}, [%4];"
                 : "=r"(r0), "=r"(r1), "=r"(r2), "=r"(r3) : "r"(addr));
}
__device__ __forceinline__ void cp16(uint32_t dst, const void* src) {
    asm volatile("cp.async.cg.shared.global [%0], [%1], 16;\n"
                 :: "r"(dst), "l"(src));
}

// ---------------------------------------------------------------------------
// Flag reset (graph-replay safe)
// ---------------------------------------------------------------------------
__global__ void zero_flags_kernel() { g_flags[threadIdx.x] = 0; }

// ---------------------------------------------------------------------------
// Pre-pass: fp32 -> fp16 (rn), 8 elems/thread
// ---------------------------------------------------------------------------
__global__ void __launch_bounds__(256)
f32_to_f16_kernel(const float* __restrict__ src, __half* __restrict__ dst,
                  int n8)
{
    int g = blockIdx.x * 256 + threadIdx.x;
    if (g >= n8) return;
    const float4* s = (const float4*)(src + (size_t)g * 8);
    float4 a = s[0], b = s[1];
    __half2 h0 = __floats2half2_rn(a.x, a.y);
    __half2 h1 = __floats2half2_rn(a.z, a.w);
    __half2 h2 = __floats2half2_rn(b.x, b.y);
    __half2 h3 = __floats2half2_rn(b.z, b.w);
    uint4 o;
    o.x = *(uint32_t*)&h0; o.y = *(uint32_t*)&h1;
    o.z = *(uint32_t*)&h2; o.w = *(uint32_t*)&h3;
    *(uint4*)(dst + (size_t)g * 8) = o;
}

// ---------------------------------------------------------------------------
// 128x256 fp16 GEMM body (NT): C[m,n] = sum_k A[m,k]*B[n,k], fp32 accum/out.
// 256 threads, 8 warps of 64x64, cp.async 5-stage, ldmatrix fragments.
// ---------------------------------------------------------------------------
__device__ __forceinline__ void gemm_body(const __half* __restrict__ Ag0,
                                          const __half* __restrict__ Bg0,
                                          float* __restrict__ Cg0,
                                          int K, int ldc)
{
    extern __shared__ char smem_dyn[];
    char* Asm = smem_dyn;
    char* Bsm = smem_dyn + NSTAGE * A_STAGE_B;
    const uint32_t aBase = (uint32_t)__cvta_generic_to_shared(Asm);
    const uint32_t bBase = (uint32_t)__cvta_generic_to_shared(Bsm);

    const int tid   = threadIdx.x;
    const int lane  = tid & 31;
    const int warp  = tid >> 5;
    const int group = lane >> 2;
    const int tig   = lane & 3;
    const int wm = (warp >> 2) * 64;   // 2 warp rows
    const int wn = (warp & 3) * 64;    // 4 warp cols

    const int lj = lane >> 3;          // ldmatrix matrix id 0..3
    const int lrr = lane & 7;
    const uint32_t fragOff =
        (uint32_t)(((lj & 1) * 8 + lrr) * ROWB + (lj >> 1) * 16);

    float c[4][8][4];
#pragma unroll
    for (int mt = 0; mt < 4; mt++)
#pragma unroll
        for (int nt = 0; nt < 8; nt++)
#pragma unroll
            for (int q = 0; q < 4; q++) c[mt][nt][q] = 0.0f;

    const int arow  = tid >> 1;
    const int ahalf = tid & 1;
    const uint32_t aOff  = (uint32_t)(arow * ROWB + ahalf * 16);
    const uint32_t bOff0 = aOff;
    const uint32_t bOff1 = (uint32_t)((arow + 128) * ROWB + ahalf * 16);
    const int niter = K >> 4;

    auto load_stage = [&](int st, int ko) {
        const uint32_t aS = aBase + (uint32_t)(st * A_STAGE_B);
        const uint32_t bS = bBase + (uint32_t)(st * B_STAGE_B);
        cp16(aS + aOff,  Ag0 + (size_t)arow * K + ko + ahalf * 8);
        cp16(bS + bOff0, Bg0 + (size_t)arow * K + ko + ahalf * 8);
        cp16(bS + bOff1, Bg0 + (size_t)(arow + 128) * K + ko + ahalf * 8);
        asm volatile("cp.async.commit_group;\n");
    };

    load_stage(0, 0);
    load_stage(1, 16);
    load_stage(2, 32);
    load_stage(3, 48);

    int st = 0, ldst = 4;
    for (int it = 0; it < niter; it++) {
        asm volatile("cp.async.wait_group 3;\n");
        __syncthreads();

        const uint32_t aT = aBase + (uint32_t)(st * A_STAGE_B);
        const uint32_t bT = bBase + (uint32_t)(st * B_STAGE_B);

        uint32_t a[4][4], bf[4][4];
#pragma unroll
        for (int mt = 0; mt < 4; mt++)
            ldsm4(a[mt][0], a[mt][1], a[mt][2], a[mt][3],
                  aT + (uint32_t)((wm + mt * 16) * ROWB) + fragOff);
#pragma unroll
        for (int bt = 0; bt < 4; bt++)
            ldsm4(bf[bt][0], bf[bt][1], bf[bt][2], bf[bt][3],
                  bT + (uint32_t)((wn + bt * 16) * ROWB) + fragOff);

#pragma unroll
        for (int mt = 0; mt < 4; mt++)
#pragma unroll
            for (int nt = 0; nt < 8; nt++) {
                const int bt = nt >> 1, s = nt & 1;
                mma_f16(c[mt][nt], a[mt], bf[bt][s], bf[bt][s + 2]);
            }

        if (it + 4 < niter)
            load_stage(ldst, (it + 4) * 16);
        else
            asm volatile("cp.async.commit_group;\n");

        st   = (st   + 1 == NSTAGE) ? 0 : st + 1;
        ldst = (ldst + 1 == NSTAGE) ? 0 : ldst + 1;
    }

#pragma unroll
    for (int mt = 0; mt < 4; mt++) {
        const int m0 = wm + mt * 16 + group;
#pragma unroll
        for (int nt = 0; nt < 8; nt++) {
            const int n0 = wn + nt * 8 + 2 * tig;
            *(float2*)(Cg0 + (size_t)m0 * ldc + n0) =
                make_float2(c[mt][nt][0], c[mt][nt][1]);
            *(float2*)(Cg0 + (size_t)(m0 + 8) * ldc + n0) =
                make_float2(c[mt][nt][2], c[mt][nt][3]);
        }
    }
}

__global__ void __launch_bounds__(256)
f16_gemm_nt(const __half* __restrict__ A, const __half* __restrict__ B,
            float* __restrict__ C, int K, int ldc)
{
    gemm_body(A + (size_t)blockIdx.y * BM * K,
              B + (size_t)blockIdx.x * BN * K,
              C + (size_t)blockIdx.y * BM * ldc + blockIdx.x * BN,
              K, ldc);
}

// ---------------------------------------------------------------------------
// Sequential recurrence with inline depthwise conv. 128 threads, one (b,head).
// Consumes proj tiles gated by g_flags. ALL proj reads use ld.global.cg
// (L2-coherent) because the producer runs concurrently in the same kernel.
// ---------------------------------------------------------------------------
__device__ void scan_body(const float* proj,
                          const float* __restrict__ cw,
                          const float* __restrict__ sw,
                          float* __restrict__ y, int bh)
{
    const int tid  = threadIdx.x;
    const int k    = tid & 63;
    const bool isf = tid < 64;
    const int head = bh & 7;
    const int b    = bh >> 3;

    __shared__ __align__(16) float h_sh[64];
    __shared__ __align__(16) float hr_sh[64];

    unsigned long long wg[32];  // Wf (f-threads) or Wr (r-threads)
    unsigned long long wz[32];  // W  (f-threads only)
    {
        const int gidx = isf ? (NHEADS + head) : (2 * NHEADS + head);
        const float* base = sw + (size_t)gidx * 64 * 64 + k;
#pragma unroll
        for (int i = 0; i < 32; i++)
            wg[i] = pk2(base[(2 * i) * 64], base[(2 * i + 1) * 64]);
        if (isf) {
            const float* bz = sw + (size_t)head * 64 * 64 + k;
#pragma unroll
            for (int i = 0; i < 32; i++)
                wz[i] = pk2(bz[(2 * i) * 64], bz[(2 * i + 1) * 64]);
        }
    }

    // conv weights for channel c = head*64+k (f-threads only)
    float c0 = 0.f, c1 = 0.f, c2 = 0.f, c3 = 0.f;
    if (isf) {
        const float* cwp = cw + (size_t)(head * HDIM + k) * 4;
        c0 = cwp[0]; c1 = cwp[1]; c2 = cwp[2]; c3 = cwp[3];
    }

    if (tid < 64) h_sh[tid] = 0.0f;

    const float* xg_ptr = proj + (size_t)b * SEQ * PROJW
                          + (isf ? STATE : 2 * STATE) + head * HDIM + k;
    const float* xraw_ptr = proj + (size_t)b * SEQ * PROJW + head * HDIM + k;
    float* y_ptr = y + (size_t)b * SEQ * STATE + head * HDIM + k;

    // wait for tiles 0 and 1 of this batch
    if (tid == 0) {
        wait_flag(&g_flags[b * 32 + 0]);
        wait_flag(&g_flags[b * 32 + 1]);
    }
    __syncthreads();

    // initial prefetch: steps 0..3 (conv window rolls; rows <0 are zero)
    float rm1 = 0.f, rm2 = 0.f, rm3 = 0.f;
    float xg_buf[4], xi_buf[4];
#pragma unroll
    for (int j = 0; j < 4; j++) {
        xg_buf[j] = ldcg(xg_ptr + (size_t)j * PROJW);
        xi_buf[j] = 0.f;
        if (isf) {
            float raw = ldcg(xraw_ptr + (size_t)j * PROJW);
            float a = fmaf(c3, raw, fmaf(c2, rm1, fmaf(c1, rm2, c0 * rm3)));
            xi_buf[j] = a * fsigmoid(a);
            rm3 = rm2; rm2 = rm1; rm1 = raw;
        }
    }

    const ulonglong2* hp  = (const ulonglong2*)h_sh;
    const ulonglong2* hrp = (const ulonglong2*)hr_sh;

    for (int t0 = 0; t0 < SEQ; t0 += 4) {
        if ((t0 & 127) == 0 && t0 > 0) {
            // ensure next tile (covers prefetch window) is ready
            int nt = (t0 >> 7) + 1; if (nt > 31) nt = 31;
            if (tid == 0) wait_flag(&g_flags[b * 32 + nt]);
            __syncthreads();
        }
#pragma unroll
        for (int j = 0; j < 4; j++) {
            const int t = t0 + j;
            const float xg  = xg_buf[j];
            const float xiv = xi_buf[j];
            int tp = t + 4; if (tp > SEQ - 1) tp = SEQ - 1;
            xg_buf[j] = ldcg(xg_ptr + (size_t)tp * PROJW);
            if (isf) {
                float raw = ldcg(xraw_ptr + (size_t)tp * PROJW);
                float a = fmaf(c3, raw, fmaf(c2, rm1, fmaf(c1, rm2, c0 * rm3)));
                xi_buf[j] = a * fsigmoid(a);
                rm3 = rm2; rm2 = rm1; rm1 = raw;
            }

            unsigned long long a0 = 0ull, a1 = 0ull, a2 = 0ull, a3 = 0ull;
#pragma unroll
            for (int i = 0; i < 8; i++) {
                ulonglong2 p0 = hp[2 * i];
                ulonglong2 p1 = hp[2 * i + 1];
                fma2(a0, p0.x, wg[4 * i + 0]);
                fma2(a1, p0.y, wg[4 * i + 1]);
                fma2(a2, p1.x, wg[4 * i + 2]);
                fma2(a3, p1.y, wg[4 * i + 3]);
            }
            const float gate =
                fsigmoid(hadd2(add2(add2(a0, a1), add2(a2, a3))) + xg);
            const float hk = h_sh[k];
            if (!isf) hr_sh[k] = hk * gate;
            __syncthreads();

            if (isf) {
                unsigned long long z0 = 0ull, z1 = 0ull, z2 = 0ull, z3 = 0ull;
#pragma unroll
                for (int i = 0; i < 8; i++) {
                    ulonglong2 p0 = hrp[2 * i];
                    ulonglong2 p1 = hrp[2 * i + 1];
                    fma2(z0, p0.x, wz[4 * i + 0]);
                    fma2(z1, p0.y, wz[4 * i + 1]);
                    fma2(z2, p1.x, wz[4 * i + 2]);
                    fma2(z3, p1.y, wz[4 * i + 3]);
                }
                const float z =
                    ftanh(hadd2(add2(add2(z0, z1), add2(z2, z3))) + xiv);
                const float hn = gate * hk + (1.0f - gate) * z;
                h_sh[k] = hn;
                y_ptr[(size_t)t * STATE] = hn;
            }
            __syncthreads();
        }
    }
}

// ---------------------------------------------------------------------------
// Fused kernel: blocks 0..31 scan; blocks 32..1055 full proj GEMM with flags.
// GEMM m-tiles ordered time-first (batch-interleaved) so the scan never waits.
// ---------------------------------------------------------------------------
__global__ void __launch_bounds__(256)
fused_scan_gemm(float* proj,
                const float* __restrict__ cw,
                const float* __restrict__ sw,
                float* __restrict__ y,
                const __half* __restrict__ xh,
                const __half* __restrict__ winh)
{
    if (blockIdx.x < 32) {
        if (threadIdx.x >= 128) return;
        scan_body(proj, cw, sw, y, blockIdx.x);
    } else {
        const int idx = blockIdx.x - 32;
        const int nt = idx & 7;                 // n-tile 0..7
        const int m_order = idx >> 3;           // 0..127, time-first order
        const int by = (m_order & 3) * 32 + (m_order >> 2);
        gemm_body(xh + (size_t)by * BM * DMODEL,
                  winh + (size_t)nt * BN * DMODEL,
                  proj + (size_t)by * BM * PROJW + nt * BN,
                  DMODEL, PROJW);
        __threadfence();
        __syncthreads();
        if (threadIdx.x == 0) atomicAdd(&g_flags[by], 1);
    }
}

// ---------------------------------------------------------------------------
// Epilogue: v = y * silu(g); rmsnorm; * norm_w; -> fp16 yn (GEMM2's A)
// ---------------------------------------------------------------------------
__global__ void __launch_bounds__(128)
epilogue_kernel(const float* __restrict__ y, const float* __restrict__ proj,
                const float* __restrict__ norm_w, __half* __restrict__ yn)
{
    const int row = blockIdx.x;
    const int tid = threadIdx.x;
    const float* yr = y    + (size_t)row * STATE;
    const float* gr = proj + (size_t)row * PROJW + 3 * STATE;

    float v[4];
    float ss = 0.0f;
#pragma unroll
    for (int q = 0; q < 4; q++) {
        int c = tid + q * 128;
        float g = gr[c];
        float val = yr[c] * g * fsigmoid(g);
        v[q] = val;
        ss += val * val;
    }
#pragma unroll
    for (int off = 16; off > 0; off >>= 1)
        ss += __shfl_xor_sync(0xffffffffu, ss, off);
    __shared__ float red[4];
    if ((tid & 31) == 0) red[tid >> 5] = ss;
    __syncthreads();
    float tot = red[0] + red[1] + red[2] + red[3];
    float scale = rsqrtf(tot * (1.0f / 512.0f) + 1e-6f);
#pragma unroll
    for (int q = 0; q < 4; q++) {
        int c = tid + q * 128;
        yn[(size_t)row * STATE + c] = __float2half_rn(v[q] * scale * norm_w[c]);
    }
}

// ---------------------------------------------------------------------------
// Launch
// ---------------------------------------------------------------------------
extern "C" void kernel_launch(void* const* d_in, const int* in_sizes, int n_in,
                              void* d_out, int out_size)
{
    const float* x      = (const float*)d_in[0];
    const float* w_in   = (const float*)d_in[1];
    const float* conv_w = (const float*)d_in[2];
    const float* sw     = (const float*)d_in[3];
    const float* norm_w = (const float*)d_in[4];
    const float* w_out  = (const float*)d_in[5];
    float* out = (float*)d_out;

    float *proj, *y;
    __half *xh, *winh, *wouth, *ynh;
    cudaGetSymbolAddress((void**)&proj,  g_proj);
    cudaGetSymbolAddress((void**)&y,     g_y);
    cudaGetSymbolAddress((void**)&xh,    g_xh);
    cudaGetSymbolAddress((void**)&winh,  g_winh);
    cudaGetSymbolAddress((void**)&wouth, g_wouth);
    cudaGetSymbolAddress((void**)&ynh,   g_ynh);

    cudaFuncSetAttribute(f16_gemm_nt,
                         cudaFuncAttributeMaxDynamicSharedMemorySize,
                         SMEM_DYN_BYTES);
    cudaFuncSetAttribute(fused_scan_gemm,
                         cudaFuncAttributeMaxDynamicSharedMemorySize,
                         SMEM_DYN_BYTES);

    // 0. reset flags + fp32 -> fp16 conversions
    zero_flags_kernel<<<1, NMTILES>>>();
    f32_to_f16_kernel<<<(ROWS * DMODEL / 8 + 255) / 256, 256>>>(
        x, xh, ROWS * DMODEL / 8);
    f32_to_f16_kernel<<<(PROJW * DMODEL / 8 + 255) / 256, 256>>>(
        w_in, winh, PROJW * DMODEL / 8);
    f32_to_f16_kernel<<<(DMODEL * STATE / 8 + 255) / 256, 256>>>(
        w_out, wouth, DMODEL * STATE / 8);

    // 1. fused: scan (32 blocks, flag-gated) + full proj GEMM (1024 blocks)
    fused_scan_gemm<<<32 + NMTILES * NTILES_N, 256, SMEM_DYN_BYTES>>>(
        proj, conv_w, sw, y, xh, winh);

    // 2. gate + rmsnorm -> ynh (fp16)
    epilogue_kernel<<<ROWS, 128>>>(y, proj, norm_w, ynh);

    // 3. out = yn @ w_out^T  (16384 x 1024 x 512)
    {
        dim3 grid(DMODEL / BN, ROWS / BM);  // 4 x 128
        f16_gemm_nt<<<grid, 256, SMEM_DYN_BYTES>>>(ynh, wouth, out,
                                                   STATE, DMODEL);
    }
}

// round 9
// speedup vs baseline: 1.7387x; 1.7387x over previous
#include <cuda_runtime.h>
#include <cuda_fp16.h>
#include <cuda_bf16.h>
#include <cstdint>

// ---------------------------------------------------------------------------
// Problem constants
// ---------------------------------------------------------------------------
#define BATCH   4
#define SEQ     4096
#define DMODEL  1024
#define NHEADS  8
#define HDIM    64
#define STATE   512            // NHEADS*HDIM
#define PROJW   2048           // 4*STATE
#define ROWS    (BATCH*SEQ)    // 16384

// GEMM tiling: block 128x256, 8 warps of 64x64, fp16 HMMA m16n8k16
#define BM 128
#define BN 256
#define NSTAGE 5
#define ROWB 48                         // padded smem row stride (bytes)
#define A_STAGE_B (BM * ROWB)           // 6144 B
#define B_STAGE_B (BN * ROWB)           // 12288 B
#define SMEM_DYN_BYTES (NSTAGE * (A_STAGE_B + B_STAGE_B))   // 92160 B

// ---------------------------------------------------------------------------
// Scratch (device globals -- no runtime allocation allowed)
// ---------------------------------------------------------------------------
__device__ float  g_proj[(size_t)ROWS * PROJW];   // [xi_raw | xf | xr | g]
__device__ float  g_xi  [(size_t)ROWS * STATE];   // conv+silu output
__device__ float  g_y   [(size_t)ROWS * STATE];   // recurrence output
__device__ __half g_xh  [(size_t)ROWS * DMODEL];  // x (fp16)
__device__ __half g_winh[(size_t)PROJW * DMODEL]; // w_in (fp16)
__device__ __half g_wouth[(size_t)DMODEL * STATE];// w_out (fp16)
__device__ __half g_ynh [(size_t)ROWS * STATE];   // gated+normed (fp16)

// ---------------------------------------------------------------------------
// Helpers (scan)
// ---------------------------------------------------------------------------
__device__ __forceinline__ unsigned long long pk2(float lo, float hi) {
    unsigned long long r;
    asm("mov.b64 %0, {%1, %2};" : "=l"(r) : "f"(lo), "f"(hi));
    return r;
}
__device__ __forceinline__ void fma2(unsigned long long& d,
                                     unsigned long long a,
                                     unsigned long long b) {
    asm("fma.rn.f32x2 %0, %1, %2, %0;" : "+l"(d) : "l"(a), "l"(b));
}
__device__ __forceinline__ unsigned long long add2(unsigned long long a,
                                                   unsigned long long b) {
    unsigned long long d;
    asm("add.rn.f32x2 %0, %1, %2;" : "=l"(d) : "l"(a), "l"(b));
    return d;
}
__device__ __forceinline__ float hadd2(unsigned long long v) {
    float a, b;
    asm("mov.b64 {%0, %1}, %2;" : "=f"(a), "=f"(b) : "l"(v));
    return a + b;
}
__device__ __forceinline__ float fsigmoid(float x) {
    return __fdividef(1.0f, 1.0f + __expf(-x));
}
// HW tanh approximation (sm_75+): single-instruction, max rel err ~2^-11
__device__ __forceinline__ float tanh_fast(float x) {
    float y;
    asm("tanh.approx.f32 %0, %1;" : "=f"(y) : "f"(x));
    return y;
}

// ---------------------------------------------------------------------------
// GEMM primitives
// ---------------------------------------------------------------------------
__device__ __forceinline__ void mma_f16(float* c, const uint32_t* a,
                                        uint32_t b0, uint32_t b1) {
    asm volatile(
        "mma.sync.aligned.m16n8k16.row.col.f32.f16.f16.f32 "
        "{%0,%1,%2,%3}, {%4,%5,%6,%7}, {%8,%9}, {%0,%1,%2,%3};\n"
        : "+f"(c[0]), "+f"(c[1]), "+f"(c[2]), "+f"(c[3])
        : "r"(a[0]), "r"(a[1]), "r"(a[2]), "r"(a[3]), "r"(b0), "r"(b1));
}
__device__ __forceinline__ void ldsm4(uint32_t& r0, uint32_t& r1,
                                      uint32_t& r2, uint32_t& r3,
                                      uint32_t addr) {
    asm volatile("ldmatrix.sync.aligned.m8n8.x4.shared.b16 "
                 "{%0,%1,%2,%3}, [%4];"
                 : "=r"(r0), "=r"(r1), "=r"(r2), "=r"(r3) : "r"(addr));
}
__device__ __forceinline__ void cp16(uint32_t dst, const void* src) {
    asm volatile("cp.async.cg.shared.global [%0], [%1], 16;\n"
                 :: "r"(dst), "l"(src));
}

// ---------------------------------------------------------------------------
// Pre-pass: fp32 -> fp16 (rn), 8 elems/thread
// ---------------------------------------------------------------------------
__global__ void __launch_bounds__(256)
f32_to_f16_kernel(const float* __restrict__ src, __half* __restrict__ dst,
                  int n8)
{
    int g = blockIdx.x * 256 + threadIdx.x;
    if (g >= n8) return;
    const float4* s = (const float4*)(src + (size_t)g * 8);
    float4 a = s[0], b = s[1];
    __half2 h0 = __floats2half2_rn(a.x, a.y);
    __half2 h1 = __floats2half2_rn(a.z, a.w);
    __half2 h2 = __floats2half2_rn(b.x, b.y);
    __half2 h3 = __floats2half2_rn(b.z, b.w);
    uint4 o;
    o.x = *(uint32_t*)&h0; o.y = *(uint32_t*)&h1;
    o.z = *(uint32_t*)&h2; o.w = *(uint32_t*)&h3;
    *(uint4*)(dst + (size_t)g * 8) = o;
}

// ---------------------------------------------------------------------------
// 128x256 fp16 GEMM body (NT): C[m,n] = sum_k A[m,k]*B[n,k], fp32 accum/out.
// 256 threads, 8 warps of 64x64, cp.async 5-stage, ldmatrix fragments.
// ---------------------------------------------------------------------------
__device__ __forceinline__ void gemm_body(const __half* __restrict__ Ag0,
                                          const __half* __restrict__ Bg0,
                                          float* __restrict__ Cg0,
                                          int K, int ldc)
{
    extern __shared__ char smem_dyn[];
    char* Asm = smem_dyn;
    char* Bsm = smem_dyn + NSTAGE * A_STAGE_B;
    const uint32_t aBase = (uint32_t)__cvta_generic_to_shared(Asm);
    const uint32_t bBase = (uint32_t)__cvta_generic_to_shared(Bsm);

    const int tid   = threadIdx.x;
    const int lane  = tid & 31;
    const int warp  = tid >> 5;
    const int group = lane >> 2;
    const int tig   = lane & 3;
    const int wm = (warp >> 2) * 64;   // 2 warp rows
    const int wn = (warp & 3) * 64;    // 4 warp cols

    const int lj = lane >> 3;          // ldmatrix matrix id 0..3
    const int lrr = lane & 7;
    const uint32_t fragOff =
        (uint32_t)(((lj & 1) * 8 + lrr) * ROWB + (lj >> 1) * 16);

    float c[4][8][4];
#pragma unroll
    for (int mt = 0; mt < 4; mt++)
#pragma unroll
        for (int nt = 0; nt < 8; nt++)
#pragma unroll
            for (int q = 0; q < 4; q++) c[mt][nt][q] = 0.0f;

    const int arow  = tid >> 1;
    const int ahalf = tid & 1;
    const uint32_t aOff  = (uint32_t)(arow * ROWB + ahalf * 16);
    const uint32_t bOff0 = aOff;
    const uint32_t bOff1 = (uint32_t)((arow + 128) * ROWB + ahalf * 16);
    const int niter = K >> 4;

    auto load_stage = [&](int st, int ko) {
        const uint32_t aS = aBase + (uint32_t)(st * A_STAGE_B);
        const uint32_t bS = bBase + (uint32_t)(st * B_STAGE_B);
        cp16(aS + aOff,  Ag0 + (size_t)arow * K + ko + ahalf * 8);
        cp16(bS + bOff0, Bg0 + (size_t)arow * K + ko + ahalf * 8);
        cp16(bS + bOff1, Bg0 + (size_t)(arow + 128) * K + ko + ahalf * 8);
        asm volatile("cp.async.commit_group;\n");
    };

    load_stage(0, 0);
    load_stage(1, 16);
    load_stage(2, 32);
    load_stage(3, 48);

    int st = 0, ldst = 4;
    for (int it = 0; it < niter; it++) {
        asm volatile("cp.async.wait_group 3;\n");
        __syncthreads();

        const uint32_t aT = aBase + (uint32_t)(st * A_STAGE_B);
        const uint32_t bT = bBase + (uint32_t)(st * B_STAGE_B);

        uint32_t a[4][4], bf[4][4];
#pragma unroll
        for (int mt = 0; mt < 4; mt++)
            ldsm4(a[mt][0], a[mt][1], a[mt][2], a[mt][3],
                  aT + (uint32_t)((wm + mt * 16) * ROWB) + fragOff);
#pragma unroll
        for (int bt = 0; bt < 4; bt++)
            ldsm4(bf[bt][0], bf[bt][1], bf[bt][2], bf[bt][3],
                  bT + (uint32_t)((wn + bt * 16) * ROWB) + fragOff);

#pragma unroll
        for (int mt = 0; mt < 4; mt++)
#pragma unroll
            for (int nt = 0; nt < 8; nt++) {
                const int bt = nt >> 1, s = nt & 1;
                mma_f16(c[mt][nt], a[mt], bf[bt][s], bf[bt][s + 2]);
            }

        if (it + 4 < niter)
            load_stage(ldst, (it + 4) * 16);
        else
            asm volatile("cp.async.commit_group;\n");

        st   = (st   + 1 == NSTAGE) ? 0 : st + 1;
        ldst = (ldst + 1 == NSTAGE) ? 0 : ldst + 1;
    }

#pragma unroll
    for (int mt = 0; mt < 4; mt++) {
        const int m0 = wm + mt * 16 + group;
#pragma unroll
        for (int nt = 0; nt < 8; nt++) {
            const int n0 = wn + nt * 8 + 2 * tig;
            *(float2*)(Cg0 + (size_t)m0 * ldc + n0) =
                make_float2(c[mt][nt][0], c[mt][nt][1]);
            *(float2*)(Cg0 + (size_t)(m0 + 8) * ldc + n0) =
                make_float2(c[mt][nt][2], c[mt][nt][3]);
        }
    }
}

__global__ void __launch_bounds__(256)
f16_gemm_nt(const __half* __restrict__ A, const __half* __restrict__ B,
            float* __restrict__ C, int K, int ldc)
{
    gemm_body(A + (size_t)blockIdx.y * BM * K,
              B + (size_t)blockIdx.x * BN * K,
              C + (size_t)blockIdx.y * BM * ldc + blockIdx.x * BN,
              K, ldc);
}

// ---------------------------------------------------------------------------
// Sequential recurrence body: 128 threads, one (b,head) per bh.
// 8-deep prefetch, 8 independent fma2 chains, tanh.approx for z.
// ---------------------------------------------------------------------------
__device__ void scan_body(const float* __restrict__ proj,
                          const float* __restrict__ xi_in,
                          const float* __restrict__ sw,
                          float* __restrict__ y, int bh)
{
    const int tid  = threadIdx.x;
    const int k    = tid & 63;
    const bool isf = tid < 64;
    const int head = bh & 7;
    const int b    = bh >> 3;

    __shared__ __align__(16) float h_sh[64];
    __shared__ __align__(16) float hr_sh[64];

    unsigned long long wg[32];  // Wf (f-threads) or Wr (r-threads)
    unsigned long long wz[32];  // W  (f-threads only)
    {
        const int gidx = isf ? (NHEADS + head) : (2 * NHEADS + head);
        const float* base = sw + (size_t)gidx * 64 * 64 + k;
#pragma unroll
        for (int i = 0; i < 32; i++)
            wg[i] = pk2(base[(2 * i) * 64], base[(2 * i + 1) * 64]);
        if (isf) {
            const float* bz = sw + (size_t)head * 64 * 64 + k;
#pragma unroll
            for (int i = 0; i < 32; i++)
                wz[i] = pk2(bz[(2 * i) * 64], bz[(2 * i + 1) * 64]);
        }
    }

    if (tid < 64) h_sh[tid] = 0.0f;
    __syncthreads();

    const float* xg_ptr = proj + (size_t)b * SEQ * PROJW
                          + (isf ? STATE : 2 * STATE) + head * HDIM + k;
    const float* xi_ptr = xi_in + (size_t)b * SEQ * STATE + head * HDIM + k;
    float* y_ptr = y + (size_t)b * SEQ * STATE + head * HDIM + k;

    // 8-deep prefetch
    float xg_buf[8], xi_buf[8];
#pragma unroll
    for (int j = 0; j < 8; j++) {
        xg_buf[j] = xg_ptr[(size_t)j * PROJW];
        xi_buf[j] = isf ? xi_ptr[(size_t)j * STATE] : 0.0f;
    }

    const ulonglong2* hp  = (const ulonglong2*)h_sh;
    const ulonglong2* hrp = (const ulonglong2*)hr_sh;

    for (int t0 = 0; t0 < SEQ; t0 += 8) {
#pragma unroll
        for (int j = 0; j < 8; j++) {
            const int t = t0 + j;
            const float xg  = xg_buf[j];
            const float xiv = xi_buf[j];
            int tp = t + 8; if (tp > SEQ - 1) tp = SEQ - 1;
            xg_buf[j] = xg_ptr[(size_t)tp * PROJW];
            if (isf) xi_buf[j] = xi_ptr[(size_t)tp * STATE];

            // phase A: gate dot over h (8 chains, depth 4)
            unsigned long long acc[8];
#pragma unroll
            for (int c = 0; c < 8; c++) acc[c] = 0ull;
#pragma unroll
            for (int i = 0; i < 8; i++) {
                ulonglong2 p0 = hp[2 * i];
                ulonglong2 p1 = hp[2 * i + 1];
                const int cb = (i & 1) * 4;
                fma2(acc[cb + 0], p0.x, wg[4 * i + 0]);
                fma2(acc[cb + 1], p0.y, wg[4 * i + 1]);
                fma2(acc[cb + 2], p1.x, wg[4 * i + 2]);
                fma2(acc[cb + 3], p1.y, wg[4 * i + 3]);
            }
            const float dotg = hadd2(
                add2(add2(add2(acc[0], acc[1]), add2(acc[2], acc[3])),
                     add2(add2(acc[4], acc[5]), add2(acc[6], acc[7]))));
            const float gate = fsigmoid(dotg + xg);
            const float hk = h_sh[k];
            if (!isf) hr_sh[k] = hk * gate;    // r-path publishes h*r
            __syncthreads();

            if (isf) {
                // phase B: z matvec over h*r
                unsigned long long zc[8];
#pragma unroll
                for (int c = 0; c < 8; c++) zc[c] = 0ull;
#pragma unroll
                for (int i = 0; i < 8; i++) {
                    ulonglong2 p0 = hrp[2 * i];
                    ulonglong2 p1 = hrp[2 * i + 1];
                    const int cb = (i & 1) * 4;
                    fma2(zc[cb + 0], p0.x, wz[4 * i + 0]);
                    fma2(zc[cb + 1], p0.y, wz[4 * i + 1]);
                    fma2(zc[cb + 2], p1.x, wz[4 * i + 2]);
                    fma2(zc[cb + 3], p1.y, wz[4 * i + 3]);
                }
                const float dotz = hadd2(
                    add2(add2(add2(zc[0], zc[1]), add2(zc[2], zc[3])),
                         add2(add2(zc[4], zc[5]), add2(zc[6], zc[7]))));
                const float z  = tanh_fast(dotz + xiv);
                const float hn = gate * hk + (1.0f - gate) * z;
                h_sh[k] = hn;
                y_ptr[(size_t)t * STATE] = hn;
            }
            __syncthreads();
        }
    }
}

// ---------------------------------------------------------------------------
// Fused: blocks 0..31 -> scan; blocks 32.. -> g-column GEMM (cols 1536..2047)
// ---------------------------------------------------------------------------
__global__ void __launch_bounds__(256)
fused_scan_ggemm(const float* __restrict__ proj_in,
                 const float* __restrict__ xi_in,
                 const float* __restrict__ sw,
                 float* __restrict__ y,
                 const __half* __restrict__ xh,
                 const __half* __restrict__ winh,
                 float* __restrict__ proj_out)
{
    if (blockIdx.x < 32) {
        if (threadIdx.x >= 128) return;
        scan_body(proj_in, xi_in, sw, y, blockIdx.x);
    } else {
        const int idx = blockIdx.x - 32;
        const int bx = idx & 1;        // 2 n-tiles (512 cols)
        const int by = idx >> 1;       // 128 m-tiles
        gemm_body(xh + (size_t)by * BM * DMODEL,
                  winh + (size_t)(3 * STATE + bx * BN) * DMODEL,
                  proj_out + (size_t)by * BM * PROJW + 3 * STATE + bx * BN,
                  DMODEL, PROJW);
    }
}

// ---------------------------------------------------------------------------
// Depthwise causal conv (K=4) over xi (= proj[:, :512]) + SiLU -> g_xi
// ---------------------------------------------------------------------------
__global__ void conv_silu_kernel(const float* __restrict__ proj,
                                 const float* __restrict__ cw,
                                 float* __restrict__ xi)
{
    int idx = blockIdx.x * 256 + threadIdx.x;           // over ROWS*STATE
    if (idx >= ROWS * STATE) return;
    int c   = idx & (STATE - 1);
    int row = idx >> 9;
    int s   = row & (SEQ - 1);
    float acc = 0.0f;
#pragma unroll
    for (int kk = 0; kk < 4; kk++) {
        int d = kk - 3;
        if (s + d >= 0)
            acc += cw[c * 4 + kk] * proj[(size_t)(row + d) * PROJW + c];
    }
    xi[idx] = acc * fsigmoid(acc);
}

// ---------------------------------------------------------------------------
// Epilogue: v = y * silu(g); rmsnorm; * norm_w; -> fp16 yn (GEMM2's A)
// ---------------------------------------------------------------------------
__global__ void __launch_bounds__(128)
epilogue_kernel(const float* __restrict__ y, const float* __restrict__ proj,
                const float* __restrict__ norm_w, __half* __restrict__ yn)
{
    const int row = blockIdx.x;
    const int tid = threadIdx.x;
    const float* yr = y    + (size_t)row * STATE;
    const float* gr = proj + (size_t)row * PROJW + 3 * STATE;

    float v[4];
    float ss = 0.0f;
#pragma unroll
    for (int q = 0; q < 4; q++) {
        int c = tid + q * 128;
        float g = gr[c];
        float val = yr[c] * g * fsigmoid(g);
        v[q] = val;
        ss += val * val;
    }
#pragma unroll
    for (int off = 16; off > 0; off >>= 1)
        ss += __shfl_xor_sync(0xffffffffu, ss, off);
    __shared__ float red[4];
    if ((tid & 31) == 0) red[tid >> 5] = ss;
    __syncthreads();
    float tot = red[0] + red[1] + red[2] + red[3];
    float scale = rsqrtf(tot * (1.0f / 512.0f) + 1e-6f);
#pragma unroll
    for (int q = 0; q < 4; q++) {
        int c = tid + q * 128;
        yn[(size_t)row * STATE + c] = __float2half_rn(v[q] * scale * norm_w[c]);
    }
}

// ---------------------------------------------------------------------------
// Launch
// ---------------------------------------------------------------------------
extern "C" void kernel_launch(void* const* d_in, const int* in_sizes, int n_in,
                              void* d_out, int out_size)
{
    const float* x      = (const float*)d_in[0];
    const float* w_in   = (const float*)d_in[1];
    const float* conv_w = (const float*)d_in[2];
    const float* sw     = (const float*)d_in[3];
    const float* norm_w = (const float*)d_in[4];
    const float* w_out  = (const float*)d_in[5];
    float* out = (float*)d_out;

    float *proj, *xi, *y;
    __half *xh, *winh, *wouth, *ynh;
    cudaGetSymbolAddress((void**)&proj,  g_proj);
    cudaGetSymbolAddress((void**)&xi,    g_xi);
    cudaGetSymbolAddress((void**)&y,     g_y);
    cudaGetSymbolAddress((void**)&xh,    g_xh);
    cudaGetSymbolAddress((void**)&winh,  g_winh);
    cudaGetSymbolAddress((void**)&wouth, g_wouth);
    cudaGetSymbolAddress((void**)&ynh,   g_ynh);

    cudaFuncSetAttribute(f16_gemm_nt,
                         cudaFuncAttributeMaxDynamicSharedMemorySize,
                         SMEM_DYN_BYTES);
    cudaFuncSetAttribute(fused_scan_ggemm,
                         cudaFuncAttributeMaxDynamicSharedMemorySize,
                         SMEM_DYN_BYTES);

    // 0. fp32 -> fp16 conversions
    f32_to_f16_kernel<<<(ROWS * DMODEL / 8 + 255) / 256, 256>>>(
        x, xh, ROWS * DMODEL / 8);
    f32_to_f16_kernel<<<(PROJW * DMODEL / 8 + 255) / 256, 256>>>(
        w_in, winh, PROJW * DMODEL / 8);
    f32_to_f16_kernel<<<(DMODEL * STATE / 8 + 255) / 256, 256>>>(
        w_out, wouth, DMODEL * STATE / 8);

    // 1. proj[:, 0:1536] = x @ w_in[0:1536]^T  (xi_raw | xf | xr)
    {
        dim3 grid(6, ROWS / BM);   // 6 n-tiles of 256 = 1536 cols
        f16_gemm_nt<<<grid, 256, SMEM_DYN_BYTES>>>(xh, winh, proj,
                                                   DMODEL, PROJW);
    }
    // 2. depthwise conv + silu -> xi  (also warms L2 for the scan)
    conv_silu_kernel<<<(ROWS * STATE) / 256, 256>>>(proj, conv_w, xi);
    // 3. fused: sequential recurrence (32 blocks) + g-column GEMM (256 blocks)
    fused_scan_ggemm<<<32 + 2 * (ROWS / BM), 256, SMEM_DYN_BYTES>>>(
        proj, xi, sw, y, xh, winh, proj);
    // 4. gate + rmsnorm -> ynh (fp16)
    epilogue_kernel<<<ROWS, 128>>>(y, proj, norm_w, ynh);
    // 5. out = yn @ w_out^T  (16384 x 1024 x 512)
    {
        dim3 grid(DMODEL / BN, ROWS / BM);  // 4 x 128
        f16_gemm_nt<<<grid, 256, SMEM_DYN_BYTES>>>(ynh, wouth, out,
                                                   STATE, DMODEL);
    }
}

// round 10
// speedup vs baseline: 1.7435x; 1.0027x over previous
#include <cuda_runtime.h>
#include <cuda_fp16.h>
#include <cuda_bf16.h>
#include <cstdint>

// ---------------------------------------------------------------------------
// Problem constants
// ---------------------------------------------------------------------------
#define BATCH   4
#define SEQ     4096
#define DMODEL  1024
#define NHEADS  8
#define HDIM    64
#define STATE   512            // NHEADS*HDIM
#define PROJW   2048           // 4*STATE
#define ROWS    (BATCH*SEQ)    // 16384

// GEMM tiling: block 128x256, 8 warps of 64x64, fp16 HMMA m16n8k16
#define BM 128
#define BN 256
#define NSTAGE 5
#define ROWB 48                         // padded smem row stride (bytes)
#define A_STAGE_B (BM * ROWB)           // 6144 B
#define B_STAGE_B (BN * ROWB)           // 12288 B
#define SMEM_DYN_BYTES (NSTAGE * (A_STAGE_B + B_STAGE_B))   // 92160 B

// ---------------------------------------------------------------------------
// Scratch (device globals -- no runtime allocation allowed)
// ---------------------------------------------------------------------------
__device__ float  g_proj[(size_t)ROWS * PROJW];   // [xi_raw | xf | xr | g]
__device__ float  g_xi  [(size_t)ROWS * STATE];   // conv+silu output
__device__ float  g_y   [(size_t)ROWS * STATE];   // recurrence output
__device__ __half g_xh  [(size_t)ROWS * DMODEL];  // x (fp16)
__device__ __half g_winh[(size_t)PROJW * DMODEL]; // w_in (fp16)
__device__ __half g_wouth[(size_t)DMODEL * STATE];// w_out (fp16)
__device__ __half g_ynh [(size_t)ROWS * STATE];   // gated+normed (fp16)

// ---------------------------------------------------------------------------
// Helpers (scan)
// ---------------------------------------------------------------------------
__device__ __forceinline__ unsigned long long pk2(float lo, float hi) {
    unsigned long long r;
    asm("mov.b64 %0, {%1, %2};" : "=l"(r) : "f"(lo), "f"(hi));
    return r;
}
__device__ __forceinline__ void fma2(unsigned long long& d,
                                     unsigned long long a,
                                     unsigned long long b) {
    asm("fma.rn.f32x2 %0, %1, %2, %0;" : "+l"(d) : "l"(a), "l"(b));
}
__device__ __forceinline__ unsigned long long add2(unsigned long long a,
                                                   unsigned long long b) {
    unsigned long long d;
    asm("add.rn.f32x2 %0, %1, %2;" : "=l"(d) : "l"(a), "l"(b));
    return d;
}
__device__ __forceinline__ float hadd2(unsigned long long v) {
    float a, b;
    asm("mov.b64 {%0, %1}, %2;" : "=f"(a), "=f"(b) : "l"(v));
    return a + b;
}
__device__ __forceinline__ float fsigmoid(float x) {
    return __fdividef(1.0f, 1.0f + __expf(-x));
}
// HW tanh approximation (sm_75+): single MUFU-class op, max rel err ~2^-11
__device__ __forceinline__ float tanh_fast(float x) {
    float y;
    asm("tanh.approx.f32 %0, %1;" : "=f"(y) : "f"(x));
    return y;
}
// sigmoid via tanh.approx: sigma(x) = 0.5 + 0.5*tanh(x/2)  (~24 cyc vs ~44)
__device__ __forceinline__ float sigmoid_fast(float x) {
    return fmaf(0.5f, tanh_fast(0.5f * x), 0.5f);
}

// ---------------------------------------------------------------------------
// GEMM primitives
// ---------------------------------------------------------------------------
__device__ __forceinline__ void mma_f16(float* c, const uint32_t* a,
                                        uint32_t b0, uint32_t b1) {
    asm volatile(
        "mma.sync.aligned.m16n8k16.row.col.f32.f16.f16.f32 "
        "{%0,%1,%2,%3}, {%4,%5,%6,%7}, {%8,%9}, {%0,%1,%2,%3};\n"
        : "+f"(c[0]), "+f"(c[1]), "+f"(c[2]), "+f"(c[3])
        : "r"(a[0]), "r"(a[1]), "r"(a[2]), "r"(a[3]), "r"(b0), "r"(b1));
}
__device__ __forceinline__ void ldsm4(uint32_t& r0, uint32_t& r1,
                                      uint32_t& r2, uint32_t& r3,
                                      uint32_t addr) {
    asm volatile("ldmatrix.sync.aligned.m8n8.x4.shared.b16 "
                 "{%0,%1,%2,%3}, [%4];"
                 : "=r"(r0), "=r"(r1), "=r"(r2), "=r"(r3) : "r"(addr));
}
__device__ __forceinline__ void cp16(uint32_t dst, const void* src) {
    asm volatile("cp.async.cg.shared.global [%0], [%1], 16;\n"
                 :: "r"(dst), "l"(src));
}

// ---------------------------------------------------------------------------
// Pre-pass: fp32 -> fp16 (rn), 8 elems/thread
// ---------------------------------------------------------------------------
__global__ void __launch_bounds__(256)
f32_to_f16_kernel(const float* __restrict__ src, __half* __restrict__ dst,
                  int n8)
{
    int g = blockIdx.x * 256 + threadIdx.x;
    if (g >= n8) return;
    const float4* s = (const float4*)(src + (size_t)g * 8);
    float4 a = s[0], b = s[1];
    __half2 h0 = __floats2half2_rn(a.x, a.y);
    __half2 h1 = __floats2half2_rn(a.z, a.w);
    __half2 h2 = __floats2half2_rn(b.x, b.y);
    __half2 h3 = __floats2half2_rn(b.z, b.w);
    uint4 o;
    o.x = *(uint32_t*)&h0; o.y = *(uint32_t*)&h1;
    o.z = *(uint32_t*)&h2; o.w = *(uint32_t*)&h3;
    *(uint4*)(dst + (size_t)g * 8) = o;
}

// ---------------------------------------------------------------------------
// 128x256 fp16 GEMM body (NT): C[m,n] = sum_k A[m,k]*B[n,k], fp32 accum/out.
// 256 threads, 8 warps of 64x64, cp.async 5-stage, ldmatrix fragments.
// ---------------------------------------------------------------------------
__device__ __forceinline__ void gemm_body(const __half* __restrict__ Ag0,
                                          const __half* __restrict__ Bg0,
                                          float* __restrict__ Cg0,
                                          int K, int ldc)
{
    extern __shared__ char smem_dyn[];
    char* Asm = smem_dyn;
    char* Bsm = smem_dyn + NSTAGE * A_STAGE_B;
    const uint32_t aBase = (uint32_t)__cvta_generic_to_shared(Asm);
    const uint32_t bBase = (uint32_t)__cvta_generic_to_shared(Bsm);

    const int tid   = threadIdx.x;
    const int lane  = tid & 31;
    const int warp  = tid >> 5;
    const int group = lane >> 2;
    const int tig   = lane & 3;
    const int wm = (warp >> 2) * 64;   // 2 warp rows
    const int wn = (warp & 3) * 64;    // 4 warp cols

    const int lj = lane >> 3;          // ldmatrix matrix id 0..3
    const int lrr = lane & 7;
    const uint32_t fragOff =
        (uint32_t)(((lj & 1) * 8 + lrr) * ROWB + (lj >> 1) * 16);

    float c[4][8][4];
#pragma unroll
    for (int mt = 0; mt < 4; mt++)
#pragma unroll
        for (int nt = 0; nt < 8; nt++)
#pragma unroll
            for (int q = 0; q < 4; q++) c[mt][nt][q] = 0.0f;

    const int arow  = tid >> 1;
    const int ahalf = tid & 1;
    const uint32_t aOff  = (uint32_t)(arow * ROWB + ahalf * 16);
    const uint32_t bOff0 = aOff;
    const uint32_t bOff1 = (uint32_t)((arow + 128) * ROWB + ahalf * 16);
    const int niter = K >> 4;

    auto load_stage = [&](int st, int ko) {
        const uint32_t aS = aBase + (uint32_t)(st * A_STAGE_B);
        const uint32_t bS = bBase + (uint32_t)(st * B_STAGE_B);
        cp16(aS + aOff,  Ag0 + (size_t)arow * K + ko + ahalf * 8);
        cp16(bS + bOff0, Bg0 + (size_t)arow * K + ko + ahalf * 8);
        cp16(bS + bOff1, Bg0 + (size_t)(arow + 128) * K + ko + ahalf * 8);
        asm volatile("cp.async.commit_group;\n");
    };

    load_stage(0, 0);
    load_stage(1, 16);
    load_stage(2, 32);
    load_stage(3, 48);

    int st = 0, ldst = 4;
    for (int it = 0; it < niter; it++) {
        asm volatile("cp.async.wait_group 3;\n");
        __syncthreads();

        const uint32_t aT = aBase + (uint32_t)(st * A_STAGE_B);
        const uint32_t bT = bBase + (uint32_t)(st * B_STAGE_B);

        uint32_t a[4][4], bf[4][4];
#pragma unroll
        for (int mt = 0; mt < 4; mt++)
            ldsm4(a[mt][0], a[mt][1], a[mt][2], a[mt][3],
                  aT + (uint32_t)((wm + mt * 16) * ROWB) + fragOff);
#pragma unroll
        for (int bt = 0; bt < 4; bt++)
            ldsm4(bf[bt][0], bf[bt][1], bf[bt][2], bf[bt][3],
                  bT + (uint32_t)((wn + bt * 16) * ROWB) + fragOff);

#pragma unroll
        for (int mt = 0; mt < 4; mt++)
#pragma unroll
            for (int nt = 0; nt < 8; nt++) {
                const int bt = nt >> 1, s = nt & 1;
                mma_f16(c[mt][nt], a[mt], bf[bt][s], bf[bt][s + 2]);
            }

        if (it + 4 < niter)
            load_stage(ldst, (it + 4) * 16);
        else
            asm volatile("cp.async.commit_group;\n");

        st   = (st   + 1 == NSTAGE) ? 0 : st + 1;
        ldst = (ldst + 1 == NSTAGE) ? 0 : ldst + 1;
    }

#pragma unroll
    for (int mt = 0; mt < 4; mt++) {
        const int m0 = wm + mt * 16 + group;
#pragma unroll
        for (int nt = 0; nt < 8; nt++) {
            const int n0 = wn + nt * 8 + 2 * tig;
            *(float2*)(Cg0 + (size_t)m0 * ldc + n0) =
                make_float2(c[mt][nt][0], c[mt][nt][1]);
            *(float2*)(Cg0 + (size_t)(m0 + 8) * ldc + n0) =
                make_float2(c[mt][nt][2], c[mt][nt][3]);
        }
    }
}

__global__ void __launch_bounds__(256)
f16_gemm_nt(const __half* __restrict__ A, const __half* __restrict__ B,
            float* __restrict__ C, int K, int ldc)
{
    gemm_body(A + (size_t)blockIdx.y * BM * K,
              B + (size_t)blockIdx.x * BN * K,
              C + (size_t)blockIdx.y * BM * ldc + blockIdx.x * BN,
              K, ldc);
}

// ---------------------------------------------------------------------------
// Sequential recurrence body: 128 threads, one (b,head) per bh.
// 3-phase step: A) both gate dots (full, 1 thread/output)
//               B) z matvec split across ALL 128 threads (half-dot each)
//               C) f threads combine partials, update h.
// Sigmoids via tanh.approx.
// ---------------------------------------------------------------------------
__device__ void scan_body(const float* __restrict__ proj,
                          const float* __restrict__ xi_in,
                          const float* __restrict__ sw,
                          float* __restrict__ y, int bh)
{
    const int tid  = threadIdx.x;
    const int k    = tid & 63;
    const int q    = tid >> 6;          // 0 = f-threads, 1 = r-threads
    const bool isf = (q == 0);
    const int head = bh & 7;
    const int b    = bh >> 3;

    __shared__ __align__(16) float h_sh[64];
    __shared__ __align__(16) float hr_sh[64];
    __shared__ __align__(16) float pz_sh[128];   // z partials, slot 2k+q

    unsigned long long wg[32];   // Wf (f) or Wr (r), full column k
    unsigned long long wzh[16];  // W column k, rows [32q, 32q+32) (all threads)
    {
        const int gidx = isf ? (NHEADS + head) : (2 * NHEADS + head);
        const float* base = sw + (size_t)gidx * 64 * 64 + k;
#pragma unroll
        for (int i = 0; i < 32; i++)
            wg[i] = pk2(base[(2 * i) * 64], base[(2 * i + 1) * 64]);
        const float* bz = sw + (size_t)head * 64 * 64 + k;
#pragma unroll
        for (int i = 0; i < 16; i++)
            wzh[i] = pk2(bz[(32 * q + 2 * i) * 64],
                         bz[(32 * q + 2 * i + 1) * 64]);
    }

    if (tid < 64) h_sh[tid] = 0.0f;
    __syncthreads();

    const float* xg_ptr = proj + (size_t)b * SEQ * PROJW
                          + (isf ? STATE : 2 * STATE) + head * HDIM + k;
    const float* xi_ptr = xi_in + (size_t)b * SEQ * STATE + head * HDIM + k;
    float* y_ptr = y + (size_t)b * SEQ * STATE + head * HDIM + k;

    // 8-deep prefetch
    float xg_buf[8], xi_buf[8];
#pragma unroll
    for (int j = 0; j < 8; j++) {
        xg_buf[j] = xg_ptr[(size_t)j * PROJW];
        xi_buf[j] = isf ? xi_ptr[(size_t)j * STATE] : 0.0f;
    }

    const ulonglong2* hp  = (const ulonglong2*)h_sh;
    const ulonglong2* hrp = (const ulonglong2*)hr_sh + q * 8;  // this half

    for (int t0 = 0; t0 < SEQ; t0 += 8) {
#pragma unroll
        for (int j = 0; j < 8; j++) {
            const int t = t0 + j;
            const float xg  = xg_buf[j];
            const float xiv = xi_buf[j];
            int tp = t + 8; if (tp > SEQ - 1) tp = SEQ - 1;
            xg_buf[j] = xg_ptr[(size_t)tp * PROJW];
            if (isf) xi_buf[j] = xi_ptr[(size_t)tp * STATE];

            // ---- phase A: gate dot over h (8 chains) ----
            unsigned long long acc[8];
#pragma unroll
            for (int c = 0; c < 8; c++) acc[c] = 0ull;
#pragma unroll
            for (int i = 0; i < 8; i++) {
                ulonglong2 p0 = hp[2 * i];
                ulonglong2 p1 = hp[2 * i + 1];
                const int cb = (i & 1) * 4;
                fma2(acc[cb + 0], p0.x, wg[4 * i + 0]);
                fma2(acc[cb + 1], p0.y, wg[4 * i + 1]);
                fma2(acc[cb + 2], p1.x, wg[4 * i + 2]);
                fma2(acc[cb + 3], p1.y, wg[4 * i + 3]);
            }
            const float dotg = hadd2(
                add2(add2(add2(acc[0], acc[1]), add2(acc[2], acc[3])),
                     add2(add2(acc[4], acc[5]), add2(acc[6], acc[7]))));
            const float gate = sigmoid_fast(dotg + xg);
            const float hk = h_sh[k];
            if (!isf) hr_sh[k] = hk * gate;    // r-path publishes h*r
            __syncthreads();                    // 1: hr visible

            // ---- phase B: half z-dot on ALL threads (rows 32q..32q+31) ----
            unsigned long long zc0 = 0ull, zc1 = 0ull, zc2 = 0ull, zc3 = 0ull;
#pragma unroll
            for (int i = 0; i < 4; i++) {
                ulonglong2 p0 = hrp[2 * i];
                ulonglong2 p1 = hrp[2 * i + 1];
                fma2(zc0, p0.x, wzh[4 * i + 0]);
                fma2(zc1, p0.y, wzh[4 * i + 1]);
                fma2(zc2, p1.x, wzh[4 * i + 2]);
                fma2(zc3, p1.y, wzh[4 * i + 3]);
            }
            pz_sh[2 * k + q] =
                hadd2(add2(add2(zc0, zc1), add2(zc2, zc3)));
            __syncthreads();                    // 2: partials visible

            // ---- phase C: combine + state update (f threads) ----
            if (isf) {
                float2 pp = *(const float2*)&pz_sh[2 * k];
                const float z  = tanh_fast(pp.x + pp.y + xiv);
                const float hn = fmaf(gate, hk - z, z);  // f*h + (1-f)*z
                h_sh[k] = hn;
                y_ptr[(size_t)t * STATE] = hn;
            }
            __syncthreads();                    // 3: new h visible
        }
    }
}

// ---------------------------------------------------------------------------
// Fused: blocks 0..31 -> scan; blocks 32.. -> g-column GEMM (cols 1536..2047)
// ---------------------------------------------------------------------------
__global__ void __launch_bounds__(256)
fused_scan_ggemm(const float* __restrict__ proj_in,
                 const float* __restrict__ xi_in,
                 const float* __restrict__ sw,
                 float* __restrict__ y,
                 const __half* __restrict__ xh,
                 const __half* __restrict__ winh,
                 float* __restrict__ proj_out)
{
    if (blockIdx.x < 32) {
        if (threadIdx.x >= 128) return;
        scan_body(proj_in, xi_in, sw, y, blockIdx.x);
    } else {
        const int idx = blockIdx.x - 32;
        const int bx = idx & 1;        // 2 n-tiles (512 cols)
        const int by = idx >> 1;       // 128 m-tiles
        gemm_body(xh + (size_t)by * BM * DMODEL,
                  winh + (size_t)(3 * STATE + bx * BN) * DMODEL,
                  proj_out + (size_t)by * BM * PROJW + 3 * STATE + bx * BN,
                  DMODEL, PROJW);
    }
}

// ---------------------------------------------------------------------------
// Depthwise causal conv (K=4) over xi (= proj[:, :512]) + SiLU -> g_xi
// ---------------------------------------------------------------------------
__global__ void conv_silu_kernel(const float* __restrict__ proj,
                                 const float* __restrict__ cw,
                                 float* __restrict__ xi)
{
    int idx = blockIdx.x * 256 + threadIdx.x;           // over ROWS*STATE
    if (idx >= ROWS * STATE) return;
    int c   = idx & (STATE - 1);
    int row = idx >> 9;
    int s   = row & (SEQ - 1);
    float acc = 0.0f;
#pragma unroll
    for (int kk = 0; kk < 4; kk++) {
        int d = kk - 3;
        if (s + d >= 0)
            acc += cw[c * 4 + kk] * proj[(size_t)(row + d) * PROJW + c];
    }
    xi[idx] = acc * fsigmoid(acc);
}

// ---------------------------------------------------------------------------
// Epilogue: v = y * silu(g); rmsnorm; * norm_w; -> fp16 yn (GEMM2's A)
// ---------------------------------------------------------------------------
__global__ void __launch_bounds__(128)
epilogue_kernel(const float* __restrict__ y, const float* __restrict__ proj,
                const float* __restrict__ norm_w, __half* __restrict__ yn)
{
    const int row = blockIdx.x;
    const int tid = threadIdx.x;
    const float* yr = y    + (size_t)row * STATE;
    const float* gr = proj + (size_t)row * PROJW + 3 * STATE;

    float v[4];
    float ss = 0.0f;
#pragma unroll
    for (int q = 0; q < 4; q++) {
        int c = tid + q * 128;
        float g = gr[c];
        float val = yr[c] * g * fsigmoid(g);
        v[q] = val;
        ss += val * val;
    }
#pragma unroll
    for (int off = 16; off > 0; off >>= 1)
        ss += __shfl_xor_sync(0xffffffffu, ss, off);
    __shared__ float red[4];
    if ((tid & 31) == 0) red[tid >> 5] = ss;
    __syncthreads();
    float tot = red[0] + red[1] + red[2] + red[3];
    float scale = rsqrtf(tot * (1.0f / 512.0f) + 1e-6f);
#pragma unroll
    for (int q = 0; q < 4; q++) {
        int c = tid + q * 128;
        yn[(size_t)row * STATE + c] = __float2half_rn(v[q] * scale * norm_w[c]);
    }
}

// ---------------------------------------------------------------------------
// Launch
// ---------------------------------------------------------------------------
extern "C" void kernel_launch(void* const* d_in, const int* in_sizes, int n_in,
                              void* d_out, int out_size)
{
    const float* x      = (const float*)d_in[0];
    const float* w_in   = (const float*)d_in[1];
    const float* conv_w = (const float*)d_in[2];
    const float* sw     = (const float*)d_in[3];
    const float* norm_w = (const float*)d_in[4];
    const float* w_out  = (const float*)d_in[5];
    float* out = (float*)d_out;

    float *proj, *xi, *y;
    __half *xh, *winh, *wouth, *ynh;
    cudaGetSymbolAddress((void**)&proj,  g_proj);
    cudaGetSymbolAddress((void**)&xi,    g_xi);
    cudaGetSymbolAddress((void**)&y,     g_y);
    cudaGetSymbolAddress((void**)&xh,    g_xh);
    cudaGetSymbolAddress((void**)&winh,  g_winh);
    cudaGetSymbolAddress((void**)&wouth, g_wouth);
    cudaGetSymbolAddress((void**)&ynh,   g_ynh);

    cudaFuncSetAttribute(f16_gemm_nt,
                         cudaFuncAttributeMaxDynamicSharedMemorySize,
                         SMEM_DYN_BYTES);
    cudaFuncSetAttribute(fused_scan_ggemm,
                         cudaFuncAttributeMaxDynamicSharedMemorySize,
                         SMEM_DYN_BYTES);

    // 0. fp32 -> fp16 conversions
    f32_to_f16_kernel<<<(ROWS * DMODEL / 8 + 255) / 256, 256>>>(
        x, xh, ROWS * DMODEL / 8);
    f32_to_f16_kernel<<<(PROJW * DMODEL / 8 + 255) / 256, 256>>>(
        w_in, winh, PROJW * DMODEL / 8);
    f32_to_f16_kernel<<<(DMODEL * STATE / 8 + 255) / 256, 256>>>(
        w_out, wouth, DMODEL * STATE / 8);

    // 1. proj[:, 0:1536] = x @ w_in[0:1536]^T  (xi_raw | xf | xr)
    {
        dim3 grid(6, ROWS / BM);   // 6 n-tiles of 256 = 1536 cols
        f16_gemm_nt<<<grid, 256, SMEM_DYN_BYTES>>>(xh, winh, proj,
                                                   DMODEL, PROJW);
    }
    // 2. depthwise conv + silu -> xi  (also warms L2 for the scan)
    conv_silu_kernel<<<(ROWS * STATE) / 256, 256>>>(proj, conv_w, xi);
    // 3. fused: sequential recurrence (32 blocks) + g-column GEMM (256 blocks)
    fused_scan_ggemm<<<32 + 2 * (ROWS / BM), 256, SMEM_DYN_BYTES>>>(
        proj, xi, sw, y, xh, winh, proj);
    // 4. gate + rmsnorm -> ynh (fp16)
    epilogue_kernel<<<ROWS, 128>>>(y, proj, norm_w, ynh);
    // 5. out = yn @ w_out^T  (16384 x 1024 x 512)
    {
        dim3 grid(DMODEL / BN, ROWS / BM);  // 4 x 128
        f16_gemm_nt<<<grid, 256, SMEM_DYN_BYTES>>>(ynh, wouth, out,
                                                   STATE, DMODEL);
    }
}